// round 3
// baseline (speedup 1.0000x reference)
#include <cuda_runtime.h>
#include <math.h>

#define T_STEPS 1000
#define BATCH   16
#define MEL     80
#define HID     512
#define NCLS    64
#define NROWS   (T_STEPS*BATCH)      // 16000

#define SCAN_CTAS   64
#define COLS_PER_CTA (HID/SCAN_CTAS) // 8

// ---------------- scratch (device globals; no allocation allowed) ----------
__device__ float    g_xn0[NROWS*MEL];
__device__ float    g_be0[NROWS*HID];     // standard layout (for xnorm1)
__device__ float    g_be0p[NROWS*HID];    // scan layout [t][cta][b][8]
__device__ float    g_xn1[NROWS*HID];
__device__ float    g_be1[NROWS*HID];     // standard layout (for head)
__device__ float    g_be1p[NROWS*HID];    // scan layout
__device__ float    g_hall[NROWS*HID];
__device__ float    g_scale1[NROWS];
__device__ float    g_err[BATCH*HID];
__device__ float    g_normp[BATCH*128];   // [b][cta*2 + half]
__device__ float    g_hzero[BATCH*HID];
__device__ __align__(256) unsigned g_flags[SCAN_CTAS];

// ---------------- zero scratch each graph replay ---------------------------
__global__ void zero_scratch() {
    int i = blockIdx.x*blockDim.x + threadIdx.x;
    if (i < SCAN_CTAS)  g_flags[i] = 0u;
    if (i < BATCH*HID)  g_hzero[i] = 0.f;
}

// ---------------- x_norm for cell0 input (feats) ---------------------------
__global__ void xnorm0_kernel(const float* __restrict__ feats) {
    int w    = (blockIdx.x*blockDim.x + threadIdx.x) >> 5;
    int lane = threadIdx.x & 31;
    if (w >= NROWS) return;
    int t = w >> 4, b = w & 15;
    const float* row = feats + ((size_t)b*T_STEPS + t)*MEL;
    float v0 = row[lane];
    float v1 = row[lane+32];
    float v2 = (lane < MEL-64) ? row[lane+64] : 0.f;
    float s = v0*v0 + v1*v1 + v2*v2;
    #pragma unroll
    for (int off = 16; off; off >>= 1) s += __shfl_xor_sync(0xffffffffu, s, off);
    float sc  = fmaxf(sqrtf(s), 1e-6f);
    float inv = 1.f/sc;
    float* o = g_xn0 + (size_t)w*MEL;
    o[lane]    = fminf(fmaxf(v0*inv, -1.f), 1.f);
    o[lane+32] = fminf(fmaxf(v1*inv, -1.f), 1.f);
    if (lane < MEL-64) o[lane+64] = fminf(fmaxf(v2*inv, -1.f), 1.f);
}

// ---------------- x_norm + scale for cell1 input (be0) ---------------------
__global__ void xnorm1_kernel() {
    int w    = (blockIdx.x*blockDim.x + threadIdx.x) >> 5;
    int lane = threadIdx.x & 31;
    if (w >= NROWS) return;
    const float4* row = (const float4*)(g_be0 + (size_t)w*HID);
    float4 v[4];
    float s = 0.f;
    #pragma unroll
    for (int i = 0; i < 4; i++) {
        v[i] = row[lane + 32*i];
        s += v[i].x*v[i].x + v[i].y*v[i].y + v[i].z*v[i].z + v[i].w*v[i].w;
    }
    #pragma unroll
    for (int off = 16; off; off >>= 1) s += __shfl_xor_sync(0xffffffffu, s, off);
    float sc = fmaxf(sqrtf(s), 1e-6f);
    if (lane == 0) g_scale1[w] = sc;
    float inv = 1.f/sc;
    float4* o = (float4*)(g_xn1 + (size_t)w*HID);
    #pragma unroll
    for (int i = 0; i < 4; i++) {
        float4 u = v[i];
        u.x = fminf(fmaxf(u.x*inv,-1.f),1.f);
        u.y = fminf(fmaxf(u.y*inv,-1.f),1.f);
        u.z = fminf(fmaxf(u.z*inv,-1.f),1.f);
        u.w = fminf(fmaxf(u.w*inv,-1.f),1.f);
        o[lane + 32*i] = u;
    }
}

// ---------------- generic tiled SGEMM: C = A(M,K) @ W(N,K)^T ---------------
__global__ __launch_bounds__(256) void sgemm_nt(
    const float* __restrict__ A, int lda,
    const float* __restrict__ W, int ldw,
    float*       __restrict__ C, int ldc,
    int K, int accumulate, const float* __restrict__ bias, int remap_head,
    float* __restrict__ C2)
{
    __shared__ float As[16][64];
    __shared__ float Ws[16][64];
    int bm = blockIdx.y*64, bn = blockIdx.x*64;
    int tid = threadIdx.x;
    int lr  = tid >> 2;
    int kq  = (tid & 3)*4;
    int tx  = tid & 15, ty = tid >> 4;
    float acc[4][4];
    #pragma unroll
    for (int i=0;i<4;i++)
        #pragma unroll
        for (int j=0;j<4;j++) acc[i][j]=0.f;

    for (int k0 = 0; k0 < K; k0 += 16) {
        float4 av = *(const float4*)(A + (size_t)(bm+lr)*lda + k0 + kq);
        float4 wv = *(const float4*)(W + (size_t)(bn+lr)*ldw + k0 + kq);
        As[kq+0][lr]=av.x; As[kq+1][lr]=av.y; As[kq+2][lr]=av.z; As[kq+3][lr]=av.w;
        Ws[kq+0][lr]=wv.x; Ws[kq+1][lr]=wv.y; Ws[kq+2][lr]=wv.z; Ws[kq+3][lr]=wv.w;
        __syncthreads();
        #pragma unroll
        for (int k = 0; k < 16; k++) {
            float4 a4 = *(float4*)&As[k][ty*4];
            float4 w4 = *(float4*)&Ws[k][tx*4];
            float ar[4] = {a4.x, a4.y, a4.z, a4.w};
            float wr[4] = {w4.x, w4.y, w4.z, w4.w};
            #pragma unroll
            for (int i=0;i<4;i++)
                #pragma unroll
                for (int j=0;j<4;j++) acc[i][j] += ar[i]*wr[j];
        }
        __syncthreads();
    }
    #pragma unroll
    for (int i = 0; i < 4; i++) {
        int r = bm + ty*4 + i;
        int orow = remap_head ? ((r & 15)*T_STEPS + (r >> 4)) : r;
        #pragma unroll
        for (int j = 0; j < 4; j++) {
            int cidx = bn + tx*4 + j;
            float val = acc[i][j];
            if (bias) val += bias[cidx];
            float* p = C + (size_t)orow*ldc + cidx;
            if (accumulate) val += *p;
            *p = val;
            if (C2) {
                int tt = r >> 4, bb = r & 15;
                C2[(((size_t)tt*SCAN_CTAS + (cidx>>3))*BATCH + bb)*8 + (cidx&7)] = val;
            }
        }
    }
}

// ---------------- cp.async helpers ------------------------------------------
__device__ __forceinline__ void cpa16(void* dst, const void* src) {
    unsigned s = (unsigned)__cvta_generic_to_shared(dst);
    asm volatile("cp.async.cg.shared.global [%0], [%1], 16;" :: "r"(s), "l"(src));
}

// ---------------- atomic-free grid barrier ----------------------------------
__device__ __forceinline__ void barrier_sync(unsigned tgt, int tid, int g) {
    __syncthreads();   // all data writes of this CTA issued
    if (tid == 0)
        asm volatile("st.release.gpu.global.u32 [%0], %1;"
                     :: "l"(g_flags + g), "r"(tgt) : "memory");
    if (tid < 16) {
        const uint4* p = reinterpret_cast<const uint4*>(g_flags) + tid;
        for (;;) {
            unsigned a,b,c,d;
            asm volatile("ld.volatile.global.v4.u32 {%0,%1,%2,%3}, [%4];"
                         : "=r"(a),"=r"(b),"=r"(c),"=r"(d) : "l"(p));
            if (a>=tgt && b>=tgt && c>=tgt && d>=tgt) break;
        }
    }
    __syncwarp();
    if (tid == 0) asm volatile("fence.acq_rel.gpu;" ::: "memory");
    __syncthreads();
}

// ---------------- inner GEMM: 4 rows x 4 cols per warp, K split on lanes ----
__device__ __forceinline__ void tile_mm(const float* __restrict__ wgt,
                                        const float* __restrict__ src,
                                        int r0, int c0, int lane, float acc[16])
{
    #pragma unroll
    for (int j = 0; j < 16; j++) acc[j] = 0.f;
    #pragma unroll
    for (int i = 0; i < 4; i++) {
        int kf = (lane + 32*i)*4;
        float4 w0 = *(const float4*)&wgt[(c0+0)*HID + kf];
        float4 w1 = *(const float4*)&wgt[(c0+1)*HID + kf];
        float4 w2 = *(const float4*)&wgt[(c0+2)*HID + kf];
        float4 w3 = *(const float4*)&wgt[(c0+3)*HID + kf];
        #pragma unroll
        for (int r = 0; r < 4; r++) {
            float4 h = *(const float4*)&src[(r0+r)*HID + kf];
            acc[r*4+0] += h.x*w0.x + h.y*w0.y + h.z*w0.z + h.w*w0.w;
            acc[r*4+1] += h.x*w1.x + h.y*w1.y + h.z*w1.z + h.w*w1.w;
            acc[r*4+2] += h.x*w2.x + h.y*w2.y + h.z*w2.z + h.w*w2.w;
            acc[r*4+3] += h.x*w3.x + h.y*w3.y + h.z*w3.z + h.w*w3.w;
        }
    }
    #pragma unroll
    for (int off = 16; off; off >>= 1) {
        #pragma unroll
        for (int j = 0; j < 16; j++)
            acc[j] += __shfl_xor_sync(0xffffffffu, acc[j], off);
    }
}

__device__ __forceinline__ float pick16(const float acc[16], int lane) {
    float v = acc[0];
    #pragma unroll
    for (int j = 1; j < 16; j++) if (lane == j) v = acc[j];
    return v;
}

// ---------------- persistent sequential scan over T ------------------------
__global__ __launch_bounds__(256, 1) void scan_kernel(
    const float* __restrict__ C1, const float* __restrict__ W1,
    const float* __restrict__ a1, const float* __restrict__ taup,
    const float* __restrict__ gamp)
{
    extern __shared__ float smf[];
    float* wC   = smf;             // 4096
    float* wW   = wC   + 4096;     // 4096
    float* hb   = wW   + 4096;     // 8192
    float* eb   = hb   + 8192;     // 8192
    float* sbe0 = eb   + 8192;     // 2*128
    float* sbe1 = sbe0 + 256;      // 2*128
    float* ssc  = sbe1 + 256;      // 2*16
    float* sga  = ssc  + 32;       // 8
    float* snorm= sga  + 8;        // 16

    const int g = blockIdx.x, tid = threadIdx.x;
    const int mbase = g*COLS_PER_CTA;

    for (int i = tid; i < COLS_PER_CTA*HID; i += 256) {
        int mm = i >> 9, k = i & (HID-1);
        wC[i] = C1[(size_t)(mbase+mm)*HID + k];
        wW[i] = W1[(size_t)(mbase+mm)*HID + k];
    }
    if (tid < COLS_PER_CTA) sga[tid] = 1.f/(1.f + expf(-a1[mbase+tid]));
    const float tau = taup[0], gam = gamp[0];

    // prefetch step 0
    {
        size_t off = (size_t)g*128;
        if (tid < 32)      cpa16(sbe0 + tid*4,        g_be0p + off + tid*4);
        else if (tid < 64) cpa16(sbe1 + (tid-32)*4,   g_be1p + off + (tid-32)*4);
        else if (tid < 68) cpa16(ssc  + (tid-64)*4,   g_scale1 + (tid-64)*4);
        asm volatile("cp.async.commit_group;");
    }
    __syncthreads();

    const int warp = tid >> 5, lane = tid & 31;
    const int r0 = (warp & 3)*4;
    const int c0 = (warp >> 2)*4;
    const int rr = lane >> 2, cc = lane & 3;

    for (int t = 0; t < T_STEPS; ++t) {
        const int cur = t & 1, nxt = 1 - cur;

        // load h_{t-1} (L2-resident, written by other SMs)
        {
            const float4* s4 = (const float4*)((t == 0) ? g_hzero
                                  : (g_hall + (size_t)(t-1)*BATCH*HID));
            float4* d4 = (float4*)hb;
            #pragma unroll
            for (int i = 0; i < 8; ++i) d4[tid + 256*i] = __ldcg(s4 + tid + 256*i);
        }
        // prefetch step t+1 (overlaps with compute + barriers)
        if (t + 1 < T_STEPS) {
            size_t off = (size_t)((t+1)*SCAN_CTAS + g)*128;
            if (tid < 32)      cpa16(sbe0 + nxt*128 + tid*4,      g_be0p + off + tid*4);
            else if (tid < 64) cpa16(sbe1 + nxt*128 + (tid-32)*4, g_be1p + off + (tid-32)*4);
            else if (tid < 68) cpa16(ssc  + nxt*16  + (tid-64)*4, g_scale1 + (size_t)(t+1)*BATCH + (tid-64)*4);
        }
        asm volatile("cp.async.commit_group;");
        asm volatile("cp.async.wait_group 1;" ::: "memory");
        __syncthreads();

        // ---- phase A: P = h @ C1^T -> error + norm partials ----
        float acc[16];
        tile_mm(wC, hb, r0, c0, lane, acc);
        if (lane < 16) {
            float v  = pick16(acc, lane);
            int b    = r0 + rr;
            int ml   = c0 + cc;
            float sc = ssc[cur*16 + b];
            float e  = sbe0[cur*128 + b*8 + ml] - tanhf(v)*sc;
            g_err[b*HID + mbase + ml] = e;
            float s2 = e*e;
            s2 += __shfl_xor_sync(0x0000ffffu, s2, 1);
            s2 += __shfl_xor_sync(0x0000ffffu, s2, 2);
            if (cc == 0) g_normp[b*128 + g*2 + (c0 >> 2)] = s2;
        }
        barrier_sync(2*(unsigned)t + 1u, tid, g);

        // ---- load full error + reduce norm partials ----
        {
            const float4* s4 = (const float4*)g_err;
            float4* d4 = (float4*)eb;
            #pragma unroll
            for (int i = 0; i < 8; ++i) d4[tid + 256*i] = __ldcg(s4 + tid + 256*i);
        }
        {
            int b = tid >> 4, j = tid & 15;
            const float4* np = (const float4*)(g_normp + b*128);
            float4 x = __ldcg(np + j);
            float4 y = __ldcg(np + 16 + j);
            float s = x.x+x.y+x.z+x.w + y.x+y.y+y.z+y.w;
            s += __shfl_xor_sync(0xffffffffu, s, 1, 16);
            s += __shfl_xor_sync(0xffffffffu, s, 2, 16);
            s += __shfl_xor_sync(0xffffffffu, s, 4, 16);
            s += __shfl_xor_sync(0xffffffffu, s, 8, 16);
            if (j == 0) snorm[b] = s;
        }
        __syncthreads();

        // ---- phase B: E = error @ W1^T -> h update ----
        float acc2[16];
        tile_mm(wW, eb, r0, c0, lane, acc2);
        if (lane < 16) {
            float v   = pick16(acc2, lane);
            int b     = r0 + rr;
            int ml    = c0 + cc;
            float sc  = ssc[cur*16 + b];
            float rel = fminf(sqrtf(snorm[b])/sc, 4.f);
            float sur = 1.f/(1.f + expf(-(rel - tau)/gam));
            float hv  = hb[b*HID + mbase + ml];
            float ih  = 0.2f*hv + 0.6f*sbe1[cur*128 + b*8 + ml] + 0.2f*sur*v;
            float gg  = sur * sga[ml];
            g_hall[((size_t)t*BATCH + b)*HID + mbase + ml] = hv*(1.f - gg) + tanhf(ih)*gg;
        }
        barrier_sync(2*(unsigned)t + 2u, tid, g);
    }
}

// ---------------- launch ----------------------------------------------------
extern "C" void kernel_launch(void* const* d_in, const int* in_sizes, int n_in,
                              void* d_out, int out_size)
{
    const float* feats  = (const float*)d_in[0];
    const float* B0     = (const float*)d_in[2];
    const float* C1     = (const float*)d_in[7];
    const float* B1     = (const float*)d_in[8];
    const float* W1     = (const float*)d_in[9];
    const float* a1     = (const float*)d_in[10];
    const float* tau1   = (const float*)d_in[11];
    const float* gam1   = (const float*)d_in[12];
    const float* head_w = (const float*)d_in[13];
    const float* head_b = (const float*)d_in[14];
    float* out = (float*)d_out;

    float *p_xn0, *p_be0, *p_be0p, *p_xn1, *p_be1, *p_be1p, *p_hall;
    cudaGetSymbolAddress((void**)&p_xn0,  g_xn0);
    cudaGetSymbolAddress((void**)&p_be0,  g_be0);
    cudaGetSymbolAddress((void**)&p_be0p, g_be0p);
    cudaGetSymbolAddress((void**)&p_xn1,  g_xn1);
    cudaGetSymbolAddress((void**)&p_be1,  g_be1);
    cudaGetSymbolAddress((void**)&p_be1p, g_be1p);
    cudaGetSymbolAddress((void**)&p_hall, g_hall);

    const int SCAN_SMEM = (4096+4096+8192+8192+256+256+32+8+16)*4;
    cudaFuncSetAttribute(scan_kernel, cudaFuncAttributeMaxDynamicSharedMemorySize, SCAN_SMEM);

    zero_scratch<<<32, 256>>>();
    xnorm0_kernel<<<(NROWS*32)/256, 256>>>(feats);

    dim3 g1(HID/64, NROWS/64);
    sgemm_nt<<<g1, 256>>>(p_xn0, MEL, B0, MEL, p_be0, HID, MEL, 0, nullptr, 0, p_be0p);
    xnorm1_kernel<<<(NROWS*32)/256, 256>>>();
    sgemm_nt<<<g1, 256>>>(p_xn1, HID, B1, HID, p_be1, HID, HID, 0, nullptr, 0, p_be1p);

    scan_kernel<<<SCAN_CTAS, 256, SCAN_SMEM>>>(C1, W1, a1, tau1, gam1);

    dim3 gh(NCLS/64, NROWS/64);
    sgemm_nt<<<gh, 256>>>(p_hall, HID, head_w,       2*HID, out, NCLS, HID, 0, nullptr, 1, nullptr);
    sgemm_nt<<<gh, 256>>>(p_be1,  HID, head_w + HID, 2*HID, out, NCLS, HID, 1, head_b, 1, nullptr);
}

// round 5
// speedup vs baseline: 1.7508x; 1.7508x over previous
#include <cuda_runtime.h>
#include <math.h>

#define T_STEPS 1000
#define BATCH   16
#define MEL     80
#define HID     512
#define NCLS    64
#define NROWS   (T_STEPS*BATCH)      // 16000

#define SCAN_CTAS   64
#define COLS_PER_CTA (HID/SCAN_CTAS) // 8

// ---------------- scratch (device globals; no allocation allowed) ----------
__device__ float    g_xn0[NROWS*MEL];
__device__ float    g_be0[NROWS*HID];
__device__ float    g_xn1[NROWS*HID];
__device__ float    g_be1[NROWS*HID];
__device__ float    g_hall[NROWS*HID];
__device__ float    g_scale1[NROWS];
__device__ float    g_err[BATCH*HID];
__device__ float    g_normp[BATCH*128];   // [b][cta*2 + half] partial norms
__device__ float    g_hzero[BATCH*HID];
__device__ unsigned g_ctr[2*T_STEPS];

// ---------------- zero scratch each graph replay ---------------------------
__global__ void zero_scratch() {
    int i = blockIdx.x*blockDim.x + threadIdx.x;
    if (i < 2*T_STEPS)  g_ctr[i]   = 0u;
    if (i < BATCH*HID)  g_hzero[i] = 0.f;
}

// ---------------- x_norm for cell0 input (feats) ---------------------------
__global__ void xnorm0_kernel(const float* __restrict__ feats) {
    int w    = (blockIdx.x*blockDim.x + threadIdx.x) >> 5;
    int lane = threadIdx.x & 31;
    if (w >= NROWS) return;
    int t = w >> 4, b = w & 15;
    const float* row = feats + ((size_t)b*T_STEPS + t)*MEL;
    float v0 = row[lane];
    float v1 = row[lane+32];
    float v2 = (lane < MEL-64) ? row[lane+64] : 0.f;
    float s = v0*v0 + v1*v1 + v2*v2;
    #pragma unroll
    for (int off = 16; off; off >>= 1) s += __shfl_xor_sync(0xffffffffu, s, off);
    float sc  = fmaxf(sqrtf(s), 1e-6f);
    float inv = 1.f/sc;
    float* o = g_xn0 + (size_t)w*MEL;
    o[lane]    = fminf(fmaxf(v0*inv, -1.f), 1.f);
    o[lane+32] = fminf(fmaxf(v1*inv, -1.f), 1.f);
    if (lane < MEL-64) o[lane+64] = fminf(fmaxf(v2*inv, -1.f), 1.f);
}

// ---------------- x_norm + scale for cell1 input (be0) ---------------------
__global__ void xnorm1_kernel() {
    int w    = (blockIdx.x*blockDim.x + threadIdx.x) >> 5;
    int lane = threadIdx.x & 31;
    if (w >= NROWS) return;
    const float4* row = (const float4*)(g_be0 + (size_t)w*HID);
    float4 v[4];
    float s = 0.f;
    #pragma unroll
    for (int i = 0; i < 4; i++) {
        v[i] = row[lane + 32*i];
        s += v[i].x*v[i].x + v[i].y*v[i].y + v[i].z*v[i].z + v[i].w*v[i].w;
    }
    #pragma unroll
    for (int off = 16; off; off >>= 1) s += __shfl_xor_sync(0xffffffffu, s, off);
    float sc = fmaxf(sqrtf(s), 1e-6f);
    if (lane == 0) g_scale1[w] = sc;
    float inv = 1.f/sc;
    float4* o = (float4*)(g_xn1 + (size_t)w*HID);
    #pragma unroll
    for (int i = 0; i < 4; i++) {
        float4 u = v[i];
        u.x = fminf(fmaxf(u.x*inv,-1.f),1.f);
        u.y = fminf(fmaxf(u.y*inv,-1.f),1.f);
        u.z = fminf(fmaxf(u.z*inv,-1.f),1.f);
        u.w = fminf(fmaxf(u.w*inv,-1.f),1.f);
        o[lane + 32*i] = u;
    }
}

// ---------------- generic tiled SGEMM: C = A(M,K) @ W(N,K)^T ---------------
__global__ __launch_bounds__(256) void sgemm_nt(
    const float* __restrict__ A, int lda,
    const float* __restrict__ W, int ldw,
    float*       __restrict__ C, int ldc,
    int K, int accumulate, const float* __restrict__ bias, int remap)
{
    __shared__ float As[16][64];
    __shared__ float Ws[16][64];
    int bm = blockIdx.y*64, bn = blockIdx.x*64;
    int tid = threadIdx.x;
    int lr  = tid >> 2;
    int kq  = (tid & 3)*4;
    int tx  = tid & 15, ty = tid >> 4;
    float acc[4][4];
    #pragma unroll
    for (int i=0;i<4;i++)
        #pragma unroll
        for (int j=0;j<4;j++) acc[i][j]=0.f;

    for (int k0 = 0; k0 < K; k0 += 16) {
        float4 av = *(const float4*)(A + (size_t)(bm+lr)*lda + k0 + kq);
        float4 wv = *(const float4*)(W + (size_t)(bn+lr)*ldw + k0 + kq);
        As[kq+0][lr]=av.x; As[kq+1][lr]=av.y; As[kq+2][lr]=av.z; As[kq+3][lr]=av.w;
        Ws[kq+0][lr]=wv.x; Ws[kq+1][lr]=wv.y; Ws[kq+2][lr]=wv.z; Ws[kq+3][lr]=wv.w;
        __syncthreads();
        #pragma unroll
        for (int k = 0; k < 16; k++) {
            float4 a4 = *(float4*)&As[k][ty*4];
            float4 w4 = *(float4*)&Ws[k][tx*4];
            float ar[4] = {a4.x, a4.y, a4.z, a4.w};
            float wr[4] = {w4.x, w4.y, w4.z, w4.w};
            #pragma unroll
            for (int i=0;i<4;i++)
                #pragma unroll
                for (int j=0;j<4;j++) acc[i][j] += ar[i]*wr[j];
        }
        __syncthreads();
    }
    #pragma unroll
    for (int i = 0; i < 4; i++) {
        int r = bm + ty*4 + i;
        int orow = remap ? ((r & 15)*T_STEPS + (r >> 4)) : r;
        #pragma unroll
        for (int j = 0; j < 4; j++) {
            int cidx = bn + tx*4 + j;
            float val = acc[i][j];
            if (bias) val += bias[cidx];
            float* p = C + (size_t)orow*ldc + cidx;
            if (accumulate) val += *p;
            *p = val;
        }
    }
}

// ---------------- grid barrier (per-instance counters, replay-safe) --------
__device__ __forceinline__ void gbar(unsigned* c) {
    __syncthreads();
    if (threadIdx.x == 0) {
        __threadfence();
        unsigned prev = atomicAdd(c, 1u);
        if (prev + 1u < SCAN_CTAS) {
            while (*((volatile unsigned*)c) < SCAN_CTAS) { }
        }
        __threadfence();
    }
    __syncthreads();
}

// ---------------- inner GEMM: 4 rows x 4 cols per warp, K split on lanes ----
__device__ __forceinline__ void tile_mm(const float* __restrict__ wgt,
                                        const float* __restrict__ src,
                                        int r0, int c0, int lane, float acc[16])
{
    #pragma unroll
    for (int j = 0; j < 16; j++) acc[j] = 0.f;
    #pragma unroll
    for (int i = 0; i < 4; i++) {
        int kf = (lane + 32*i)*4;
        float4 w0 = *(const float4*)&wgt[(c0+0)*HID + kf];
        float4 w1 = *(const float4*)&wgt[(c0+1)*HID + kf];
        float4 w2 = *(const float4*)&wgt[(c0+2)*HID + kf];
        float4 w3 = *(const float4*)&wgt[(c0+3)*HID + kf];
        #pragma unroll
        for (int r = 0; r < 4; r++) {
            float4 h = *(const float4*)&src[(r0+r)*HID + kf];
            acc[r*4+0] += h.x*w0.x + h.y*w0.y + h.z*w0.z + h.w*w0.w;
            acc[r*4+1] += h.x*w1.x + h.y*w1.y + h.z*w1.z + h.w*w1.w;
            acc[r*4+2] += h.x*w2.x + h.y*w2.y + h.z*w2.z + h.w*w2.w;
            acc[r*4+3] += h.x*w3.x + h.y*w3.y + h.z*w3.z + h.w*w3.w;
        }
    }
    #pragma unroll
    for (int off = 16; off; off >>= 1) {
        #pragma unroll
        for (int j = 0; j < 16; j++)
            acc[j] += __shfl_xor_sync(0xffffffffu, acc[j], off);
    }
}

__device__ __forceinline__ float pick16(const float acc[16], int lane) {
    float v = acc[0];
    #pragma unroll
    for (int j = 1; j < 16; j++) if (lane == j) v = acc[j];
    return v;
}

// ---------------- persistent sequential scan over T ------------------------
__global__ __launch_bounds__(256, 1) void scan_kernel(
    const float* __restrict__ C1, const float* __restrict__ W1,
    const float* __restrict__ a1, const float* __restrict__ taup,
    const float* __restrict__ gamp)
{
    extern __shared__ float sm[];
    float* wC   = sm;                          // 8*512
    float* wW   = wC + COLS_PER_CTA*HID;       // 8*512
    float* hb   = wW + COLS_PER_CTA*HID;       // 16*512 (h_{t-1})
    float* eb   = hb + BATCH*HID;              // 16*512 (error)
    float* sga  = eb + BATCH*HID;              // 8
    float* snorm= sga + COLS_PER_CTA;          // 16

    const int g = blockIdx.x, tid = threadIdx.x;
    const int mbase = g*COLS_PER_CTA;

    for (int i = tid; i < COLS_PER_CTA*HID; i += 256) {
        int mm = i >> 9, k = i & (HID-1);
        wC[i] = C1[(size_t)(mbase+mm)*HID + k];
        wW[i] = W1[(size_t)(mbase+mm)*HID + k];
    }
    if (tid < COLS_PER_CTA) sga[tid] = 1.f/(1.f + expf(-a1[mbase+tid]));
    const float tau = taup[0], gam = gamp[0];
    __syncthreads();

    const int warp = tid >> 5, lane = tid & 31;
    const int r0 = (warp & 3)*4;      // batch-row group
    const int c0 = (warp >> 2)*4;     // col group within CTA slice
    const int rr = lane >> 2, cc = lane & 3;
    const int bql = r0 + rr;                  // this lane's batch row (lane<16)
    const int mql = mbase + c0 + cc;          // this lane's output column

    for (int t = 0; t < T_STEPS; ++t) {
        // ---- register prefetch of per-step DRAM operands (hidden by GEMM) --
        float pb0 = 0.f, pb1 = 0.f, psc = 1.f;
        if (lane < 16) {
            size_t row = (size_t)t*BATCH + bql;
            pb0 = __ldcg(&g_be0[row*HID + mql]);
            pb1 = __ldcg(&g_be1[row*HID + mql]);
            psc = __ldcg(&g_scale1[row]);
        }

        // ---- broadcast-load full h_{t-1} ----
        {
            const float4* s4 = (const float4*)((t == 0) ? g_hzero
                                  : (g_hall + (size_t)(t-1)*BATCH*HID));
            float4* d4 = (float4*)hb;
            #pragma unroll
            for (int i = 0; i < 8; ++i) d4[tid + 256*i] = __ldcg(s4 + tid + 256*i);
        }
        __syncthreads();

        // ---- phase A: P = h @ C1^T -> error + norm partials ----------------
        float acc[16];
        tile_mm(wC, hb, r0, c0, lane, acc);
        if (lane < 16) {
            float v = pick16(acc, lane);
            float e = pb0 - tanhf(v)*psc;
            g_err[bql*HID + mql] = e;
            float s2 = e*e;
            s2 += __shfl_xor_sync(0x0000ffffu, s2, 1);
            s2 += __shfl_xor_sync(0x0000ffffu, s2, 2);
            if (cc == 0) g_normp[bql*128 + g*2 + (c0 >> 2)] = s2;
        }
        gbar(&g_ctr[2*t]);

        // ---- load full error + reduce norm partials ------------------------
        {
            const float4* s4 = (const float4*)g_err;
            float4* d4 = (float4*)eb;
            #pragma unroll
            for (int i = 0; i < 8; ++i) d4[tid + 256*i] = __ldcg(s4 + tid + 256*i);
        }
        {
            int b = tid >> 4, j = tid & 15;
            const float4* np = (const float4*)(g_normp + b*128);
            float4 x = __ldcg(np + j);
            float4 y = __ldcg(np + 16 + j);
            float s = x.x+x.y+x.z+x.w + y.x+y.y+y.z+y.w;
            s += __shfl_xor_sync(0xffffffffu, s, 1, 16);
            s += __shfl_xor_sync(0xffffffffu, s, 2, 16);
            s += __shfl_xor_sync(0xffffffffu, s, 4, 16);
            s += __shfl_xor_sync(0xffffffffu, s, 8, 16);
            if (j == 0) snorm[b] = s;
        }
        __syncthreads();

        // ---- phase B: E = error @ W1^T -> h update -------------------------
        float acc2[16];
        tile_mm(wW, eb, r0, c0, lane, acc2);
        if (lane < 16) {
            float v   = pick16(acc2, lane);
            float rel = fminf(sqrtf(snorm[bql])/psc, 4.f);
            float sur = 1.f/(1.f + expf(-(rel - tau)/gam));
            float hv  = hb[bql*HID + mql];
            float ih  = 0.2f*hv + 0.6f*pb1 + 0.2f*sur*v;
            float gg  = sur * sga[c0 + cc];
            g_hall[((size_t)t*BATCH + bql)*HID + mql] = hv*(1.f - gg) + tanhf(ih)*gg;
        }
        gbar(&g_ctr[2*t + 1]);
    }
}

// ---------------- launch ----------------------------------------------------
extern "C" void kernel_launch(void* const* d_in, const int* in_sizes, int n_in,
                              void* d_out, int out_size)
{
    const float* feats  = (const float*)d_in[0];
    const float* B0     = (const float*)d_in[2];
    const float* C1     = (const float*)d_in[7];
    const float* B1     = (const float*)d_in[8];
    const float* W1     = (const float*)d_in[9];
    const float* a1     = (const float*)d_in[10];
    const float* tau1   = (const float*)d_in[11];
    const float* gam1   = (const float*)d_in[12];
    const float* head_w = (const float*)d_in[13];
    const float* head_b = (const float*)d_in[14];
    float* out = (float*)d_out;

    float *p_xn0, *p_be0, *p_xn1, *p_be1, *p_hall;
    cudaGetSymbolAddress((void**)&p_xn0,  g_xn0);
    cudaGetSymbolAddress((void**)&p_be0,  g_be0);
    cudaGetSymbolAddress((void**)&p_xn1,  g_xn1);
    cudaGetSymbolAddress((void**)&p_be1,  g_be1);
    cudaGetSymbolAddress((void**)&p_hall, g_hall);

    const int SCAN_SMEM = (2*COLS_PER_CTA*HID + 2*BATCH*HID + COLS_PER_CTA + 16)*4;
    cudaFuncSetAttribute(scan_kernel, cudaFuncAttributeMaxDynamicSharedMemorySize, SCAN_SMEM);

    zero_scratch<<<64, 256>>>();
    xnorm0_kernel<<<(NROWS*32)/256, 256>>>(feats);

    dim3 g1(HID/64, NROWS/64);
    sgemm_nt<<<g1, 256>>>(p_xn0, MEL, B0, MEL, p_be0, HID, MEL, 0, nullptr, 0);
    xnorm1_kernel<<<(NROWS*32)/256, 256>>>();
    sgemm_nt<<<g1, 256>>>(p_xn1, HID, B1, HID, p_be1, HID, HID, 0, nullptr, 0);

    scan_kernel<<<SCAN_CTAS, 256, SCAN_SMEM>>>(C1, W1, a1, tau1, gam1);

    dim3 gh(NCLS/64, NROWS/64);
    sgemm_nt<<<gh, 256>>>(p_hall, HID, head_w,       2*HID, out, NCLS, HID, 0, nullptr, 1);
    sgemm_nt<<<gh, 256>>>(p_be1,  HID, head_w + HID, 2*HID, out, NCLS, HID, 1, head_b, 1);
}